// round 15
// baseline (speedup 1.0000x reference)
#include <cuda_runtime.h>
#include <cuda_fp16.h>
#include <math.h>
#include <stdint.h>

// ---------------------------------------------------------------------------
// MultiHeadAttention: x@Wq/Wk/Wv -> causal flash attention -> @Wo
// B=4, S=2048, E=1024, H=16, Hs=64. fp32 I/O, FP16 tensor-core math.
// R15: revert R14 fp16-acc (no rate gain, precision cost). R13 base +
//      (a) l-ones-MMA replaced by fp32 ALU sums (HMMA binds; ALU has slack),
//      (b) prep x-conversion with 4x ILP (was MLP=1 latency-bound).
// ---------------------------------------------------------------------------

#define BATCH 4
#define SEQ   2048
#define EMBD  1024
#define NHEAD 16
#define HDIM  64
#define MROWS (BATCH*SEQ)   // 8192

#define QSCALE 0.18033688011112042f   // 0.125 * log2(e)

__device__ __align__(256) __half g_Q[MROWS * EMBD];
__device__ __align__(256) __half g_K[MROWS * EMBD];
__device__ __align__(256) __half g_V[MROWS * EMBD];
__device__ __align__(256) __half g_A[MROWS * EMBD];
__device__ __align__(256) __half g_X[MROWS * EMBD];
__device__ __align__(256) __half g_W[4 * EMBD * EMBD];   // fp16, transposed [n][k]

__device__ __forceinline__ uint32_t s2u(const void* p) {
    return (uint32_t)__cvta_generic_to_shared(p);
}
#define CP16(dst, src) \
    asm volatile("cp.async.cg.shared.global [%0], [%1], 16;\n" :: "r"(dst), "l"(src))
#define CP_COMMIT()  asm volatile("cp.async.commit_group;\n" ::: "memory")
#define CP_WAIT(n)   asm volatile("cp.async.wait_group %0;\n" :: "n"(n) : "memory")

#define LDSM4(r, addr) \
    asm volatile("ldmatrix.sync.aligned.m8n8.x4.shared.b16 {%0,%1,%2,%3}, [%4];" \
        : "=r"((r)[0]), "=r"((r)[1]), "=r"((r)[2]), "=r"((r)[3]) : "r"(addr))
#define LDSM4T(r, addr) \
    asm volatile("ldmatrix.sync.aligned.m8n8.x4.trans.shared.b16 {%0,%1,%2,%3}, [%4];" \
        : "=r"((r)[0]), "=r"((r)[1]), "=r"((r)[2]), "=r"((r)[3]) : "r"(addr))

__device__ __forceinline__ void mma16(float* c, const unsigned* a, const unsigned* b) {
    asm volatile(
        "mma.sync.aligned.m16n8k16.row.col.f32.f16.f16.f32 "
        "{%0,%1,%2,%3}, {%4,%5,%6,%7}, {%8,%9}, {%0,%1,%2,%3};\n"
        : "+f"(c[0]), "+f"(c[1]), "+f"(c[2]), "+f"(c[3])
        : "r"(a[0]), "r"(a[1]), "r"(a[2]), "r"(a[3]),
          "r"(b[0]), "r"(b[1]));
}

__device__ __forceinline__ unsigned pack_h2(float lo, float hi) {
    __half2 h = __floats2half2_rn(lo, hi);
    return *(unsigned*)&h;
}

__device__ __forceinline__ float ex2f(float x) {
    float y;
    asm("ex2.approx.f32 %0, %1;" : "=f"(y) : "f"(x));
    return y;
}

__device__ __forceinline__ unsigned hex2(unsigned x) {
    unsigned y;
    asm("ex2.approx.f16x2 %0, %1;" : "=r"(y) : "r"(x));
    return y;
}

// ---------------------------------------------------------------------------
// Merged pre-pass: blocks [0,2048) convert x -> fp16 with 4x ILP;
// blocks [2048,6144) round+transpose the 4 weight matrices to fp16 [n][k].
// ---------------------------------------------------------------------------
#define XBLKS4 2048   // (MROWS*EMBD/4) / 256 / 4
__global__ __launch_bounds__(256) void prep(
    const float4* __restrict__ x, uint2* __restrict__ xout,
    const float* __restrict__ w0, const float* __restrict__ w1,
    const float* __restrict__ w2, const float* __restrict__ w3,
    __half* __restrict__ wout)
{
    __shared__ float t[32][33];
    const int bid = blockIdx.x;
    if (bid < XBLKS4) {
        int i = bid * 1024 + threadIdx.x;
        float4 v0 = x[i];
        float4 v1 = x[i + 256];
        float4 v2 = x[i + 512];
        float4 v3 = x[i + 768];
        xout[i]       = make_uint2(pack_h2(v0.x, v0.y), pack_h2(v0.z, v0.w));
        xout[i + 256] = make_uint2(pack_h2(v1.x, v1.y), pack_h2(v1.z, v1.w));
        xout[i + 512] = make_uint2(pack_h2(v2.x, v2.y), pack_h2(v2.z, v2.w));
        xout[i + 768] = make_uint2(pack_h2(v3.x, v3.y), pack_h2(v3.z, v3.w));
    } else {
        const int wid = bid - XBLKS4;         // 0..4095
        const int z   = wid >> 10;
        const int rem = wid & 1023;
        const int bx  = (rem & 31) * 32;
        const int by  = (rem >> 5) * 32;
        const float* in = (z == 0) ? w0 : (z == 1) ? w1 : (z == 2) ? w2 : w3;
        __half* o = wout + (size_t)z * EMBD * EMBD;
        int tx = threadIdx.x & 31, ty = threadIdx.x >> 5;
        #pragma unroll
        for (int i = 0; i < 32; i += 8)
            t[ty + i][tx] = in[(size_t)(by + ty + i) * EMBD + bx + tx];
        __syncthreads();
        #pragma unroll
        for (int i = 0; i < 32; i += 8)
            o[(size_t)(bx + ty + i) * EMBD + by + tx] = __float2half_rn(t[tx][ty + i]);
    }
}

// ---------------------------------------------------------------------------
// FP16 GEMM body. CTA 128x128, BK=64, 3-stage cp.async, LDSM fragments.
// ---------------------------------------------------------------------------
#define RSTR 144
#define TILE_B (128 * RSTR)
#define STG_BYTES (2 * TILE_B)
#define GST 3
#define GSMEM (GST * STG_BYTES)        // 110592

template<bool HALF_OUT>
__device__ __forceinline__ void gemm_body(
    const __half* __restrict__ A, const __half* __restrict__ Bt, void* __restrict__ Cv,
    float oscale, int m0, int n0)
{
    extern __shared__ __align__(1024) unsigned char sgm[];

    const int tid  = threadIdx.x;
    const int warp = tid >> 5;
    const int lane = tid & 31;
    const int l4   = lane >> 2;
    const int lm4  = lane & 3;
    const int wm0  = (warp >> 1) * 32;
    const int wn0  = (warp & 1) * 64;

    const int lrow = lane & 15;
    const int lcol = (lane >> 4) * 16;

    float acc[2][8][4];
    #pragma unroll
    for (int mi = 0; mi < 2; mi++)
        #pragma unroll
        for (int ni = 0; ni < 8; ni++)
            #pragma unroll
            for (int q = 0; q < 4; q++) acc[mi][ni][q] = 0.0f;

    const uint32_t sbase = s2u(sgm);

    auto load_stage = [&](int s, int k0) {
        uint32_t ab = sbase + s * STG_BYTES;
        uint32_t bb = ab + TILE_B;
        #pragma unroll
        for (int t = 0; t < 4; t++) {
            int id = tid + t * 256;
            int r = id >> 3;
            int c = (id & 7) * 8;
            CP16(ab + r * RSTR + c * 2, A  + (size_t)(m0 + r) * EMBD + k0 + c);
        }
        #pragma unroll
        for (int t = 0; t < 4; t++) {
            int id = tid + t * 256;
            int r = id >> 3;
            int c = (id & 7) * 8;
            CP16(bb + r * RSTR + c * 2, Bt + (size_t)(n0 + r) * EMBD + k0 + c);
        }
        CP_COMMIT();
    };

    load_stage(0, 0);
    load_stage(1, 64);

    const int KT = EMBD / 64;  // 16
    for (int kt = 0; kt < KT; kt++) {
        const int s = kt % GST;
        if (kt < KT - 1) { CP_WAIT(1); } else { CP_WAIT(0); }
        __syncthreads();
        if (kt + 2 < KT) load_stage((kt + 2) % GST, (kt + 2) * 64);

        const uint32_t ab   = sbase + s * STG_BYTES;
        const uint32_t aoff = ab + (wm0 + lrow) * RSTR + lcol;
        const uint32_t boff = ab + TILE_B + (wn0 + lrow) * RSTR + lcol;

        #pragma unroll
        for (int kk = 0; kk < 4; kk++) {
            unsigned a0[4], a1[4];
            LDSM4(a0, aoff + kk * 32);
            LDSM4(a1, aoff + 16 * RSTR + kk * 32);
            unsigned bf[4][4];
            #pragma unroll
            for (int ng = 0; ng < 4; ng++)
                LDSM4(bf[ng], boff + ng * 16 * RSTR + kk * 32);
            #pragma unroll
            for (int ni = 0; ni < 8; ni++) {
                unsigned b2[2] = { bf[ni >> 1][ni & 1], bf[ni >> 1][(ni & 1) + 2] };
                mma16(acc[0][ni], a0, b2);
                mma16(acc[1][ni], a1, b2);
            }
        }
    }

    #pragma unroll
    for (int mi = 0; mi < 2; mi++) {
        #pragma unroll
        for (int ni = 0; ni < 8; ni++) {
            int row = m0 + wm0 + mi * 16 + l4;
            int col = n0 + wn0 + ni * 8 + lm4 * 2;
            if (HALF_OUT) {
                __half* C = (__half*)Cv;
                *(unsigned*)&C[(size_t)row * EMBD + col] =
                    pack_h2(acc[mi][ni][0] * oscale, acc[mi][ni][1] * oscale);
                *(unsigned*)&C[(size_t)(row + 8) * EMBD + col] =
                    pack_h2(acc[mi][ni][2] * oscale, acc[mi][ni][3] * oscale);
            } else {
                float* C = (float*)Cv;
                *(float2*)&C[(size_t)row * EMBD + col] =
                    make_float2(acc[mi][ni][0], acc[mi][ni][1]);
                *(float2*)&C[(size_t)(row + 8) * EMBD + col] =
                    make_float2(acc[mi][ni][2], acc[mi][ni][3]);
            }
        }
    }
}

__global__ __launch_bounds__(256, 2) void gemm_qkv(
    const __half* __restrict__ X, const __half* __restrict__ Wt,
    __half* __restrict__ C0, __half* __restrict__ C1, __half* __restrict__ C2)
{
    const int z  = blockIdx.x % 3;
    const int n0 = (blockIdx.x / 3) * 128;
    const int m0 = blockIdx.y * 128;
    const __half* Bt = Wt + (size_t)z * EMBD * EMBD;
    __half* C = (z == 0) ? C0 : (z == 1) ? C1 : C2;
    float sc = (z == 0) ? QSCALE : 1.0f;
    gemm_body<true>(X, Bt, C, sc, m0, n0);
}

__global__ __launch_bounds__(256, 2) void gemm_out(
    const __half* __restrict__ A, const __half* __restrict__ Wt, float* __restrict__ C)
{
    gemm_body<false>(A, Wt, C, 1.0f, blockIdx.y * 128, blockIdx.x * 128);
}

// ---------------------------------------------------------------------------
// Causal flash attention. One CTA = 128 q-rows of one (b,h), 128 threads =
// 4 warps x 32 q-rows. 128-key blocks per barrier pair. Q fragments hoisted.
// l computed via fp32 ALU sums of P (frees 6% of HMMA vs ones-MMA).
// ---------------------------------------------------------------------------
#define QTB (128 * RSTR)               // 18432
#define KTB (64 * RSTR)                // 9216 per 64-key subtile
#define KVBLK (2 * KTB)                // 128-key block
#define ATTN_SMEM (QTB + 4 * KVBLK)    // 92160 bytes

__global__ __launch_bounds__(128, 2) void attn_flash(
    const __half* __restrict__ Q, const __half* __restrict__ K,
    const __half* __restrict__ V, __half* __restrict__ O)
{
    extern __shared__ __align__(1024) unsigned char sgm[];
    const uint32_t qbase = s2u(sgm);
    const uint32_t kbase = qbase + QTB;
    const uint32_t vbase = kbase + 2 * KVBLK;

    const int tid  = threadIdx.x;
    const int warp = tid >> 5;
    const int lane = tid & 31;
    const int l4   = lane >> 2;
    const int lm4  = lane & 3;
    const int w32  = warp * 32;

    const int lrow = lane & 15;
    const int lcol = (lane >> 4) * 16;

    const int qb = (gridDim.x - 1) - blockIdx.x;   // longest blocks first
    const int q0 = qb * 128;
    const int bh = blockIdx.y;
    const int b  = bh >> 4;
    const int h  = bh & 15;
    const size_t headoff = (size_t)b * SEQ * EMBD + (size_t)h * HDIM;

    // Load Q tile (128 x 64 fp16)
    #pragma unroll
    for (int t = 0; t < 8; t++) {
        int idx = tid + t * 128;
        int r = idx >> 3;
        int c = (idx & 7) * 8;
        *(uint4*)(sgm + r * RSTR + c * 2) =
            *(const uint4*)(Q + headoff + (size_t)(q0 + r) * EMBD + c);
    }

    auto load_kv2 = [&](int jj, int s) {
        #pragma unroll
        for (int t = 0; t < 8; t++) {
            int id = tid + t * 128;
            int r = id >> 3;
            int c = (id & 7) * 8;
            CP16(kbase + s * KVBLK + r * RSTR + c * 2,
                 K + headoff + (size_t)(jj * 128 + r) * EMBD + c);
        }
        #pragma unroll
        for (int t = 0; t < 8; t++) {
            int id = tid + t * 128;
            int r = id >> 3;
            int c = (id & 7) * 8;
            CP16(vbase + s * KVBLK + r * RSTR + c * 2,
                 V + headoff + (size_t)(jj * 128 + r) * EMBD + c);
        }
        CP_COMMIT();
    };

    float m[2][2] = {{-INFINITY, -INFINITY}, {-INFINITY, -INFINITY}};
    float o[2][8][4];
    float l[2][2];   // l[mi][0]=rows l4, l[mi][1]=rows l4+8
    #pragma unroll
    for (int mi = 0; mi < 2; mi++) {
        #pragma unroll
        for (int ni = 0; ni < 8; ni++)
            #pragma unroll
            for (int q = 0; q < 4; q++) o[mi][ni][q] = 0.0f;
        l[mi][0] = 0.0f;
        l[mi][1] = 0.0f;
    }

    const int njj = qb + 1;
    load_kv2(0, 0);

    // Hoist Q fragments into registers (loop-invariant across all subtiles)
    __syncthreads();
    unsigned qf[2][4][4];
    {
        const uint32_t qoff0 = qbase + (w32 + lrow) * RSTR + lcol;
        const uint32_t qoff1 = qoff0 + 16 * RSTR;
        #pragma unroll
        for (int kk = 0; kk < 4; kk++) {
            LDSM4(qf[0][kk], qoff0 + kk * 32);
            LDSM4(qf[1][kk], qoff1 + kk * 32);
        }
    }

    for (int jj = 0; jj < njj; jj++) {
        CP_WAIT(0);
        __syncthreads();
        if (jj + 1 < njj) load_kv2(jj + 1, (jj + 1) & 1);

        #pragma unroll
        for (int hs = 0; hs < 2; hs++) {
            const int j = 2 * jj + hs;

            if (j * 64 > q0 + w32 + 31) continue;

            const uint32_t koff = kbase + (jj & 1) * KVBLK + hs * KTB
                                + lrow * RSTR + lcol;
            const uint32_t voff = vbase + (jj & 1) * KVBLK + hs * KTB
                                + lrow * RSTR + lcol;

            // S = Q K^T (warp: 32 q-rows x 64 keys)
            float s[2][8][4];
            #pragma unroll
            for (int mi = 0; mi < 2; mi++)
                #pragma unroll
                for (int ni = 0; ni < 8; ni++)
                    #pragma unroll
                    for (int q = 0; q < 4; q++) s[mi][ni][q] = 0.0f;

            #pragma unroll
            for (int kk = 0; kk < 4; kk++) {
                unsigned bf[4][4];
                #pragma unroll
                for (int ng = 0; ng < 4; ng++)
                    LDSM4(bf[ng], koff + ng * 16 * RSTR + kk * 32);
                #pragma unroll
                for (int ni = 0; ni < 8; ni++) {
                    unsigned b2[2] = { bf[ni >> 1][ni & 1], bf[ni >> 1][(ni & 1) + 2] };
                    mma16(s[0][ni], qf[0][kk], b2);
                    mma16(s[1][ni], qf[1][kk], b2);
                }
            }

            // Causal mask (diag subtiles only; warp-uniform)
            if (j * 64 + 63 > q0 + w32) {
                #pragma unroll
                for (int mi = 0; mi < 2; mi++) {
                    const int g0 = q0 + w32 + mi * 16 + l4;
                    const int g1 = g0 + 8;
                    #pragma unroll
                    for (int ni = 0; ni < 8; ni++) {
                        int gc = j * 64 + ni * 8 + lm4 * 2;
                        if (gc     > g0) s[mi][ni][0] = -INFINITY;
                        if (gc + 1 > g0) s[mi][ni][1] = -INFINITY;
                        if (gc     > g1) s[mi][ni][2] = -INFINITY;
                        if (gc + 1 > g1) s[mi][ni][3] = -INFINITY;
                    }
                }
            }

            // Row max + online rescale (per mfrag, per half)
            float a[2][2], nm[2][2];
            #pragma unroll
            for (int mi = 0; mi < 2; mi++) {
                float rm0 = -INFINITY, rm1 = -INFINITY;
                #pragma unroll
                for (int ni = 0; ni < 8; ni++) {
                    rm0 = fmaxf(rm0, fmaxf(s[mi][ni][0], s[mi][ni][1]));
                    rm1 = fmaxf(rm1, fmaxf(s[mi][ni][2], s[mi][ni][3]));
                }
                #pragma unroll
                for (int off = 1; off < 4; off <<= 1) {
                    rm0 = fmaxf(rm0, __shfl_xor_sync(0xffffffffu, rm0, off));
                    rm1 = fmaxf(rm1, __shfl_xor_sync(0xffffffffu, rm1, off));
                }
                nm[mi][0] = fmaxf(m[mi][0], rm0);
                nm[mi][1] = fmaxf(m[mi][1], rm1);
                a[mi][0] = ex2f(m[mi][0] - nm[mi][0]);
                a[mi][1] = ex2f(m[mi][1] - nm[mi][1]);
                m[mi][0] = nm[mi][0];
                m[mi][1] = nm[mi][1];
            }

            bool noresc = (a[0][0] == 1.0f) && (a[0][1] == 1.0f)
                       && (a[1][0] == 1.0f) && (a[1][1] == 1.0f);
            if (!__all_sync(0xffffffffu, noresc)) {
                #pragma unroll
                for (int mi = 0; mi < 2; mi++) {
                    #pragma unroll
                    for (int ni = 0; ni < 8; ni++) {
                        o[mi][ni][0] *= a[mi][0]; o[mi][ni][1] *= a[mi][0];
                        o[mi][ni][2] *= a[mi][1]; o[mi][ni][3] *= a[mi][1];
                    }
                    l[mi][0] *= a[mi][0];
                    l[mi][1] *= a[mi][1];
                }
            }

            // P = 2^(s-m) via packed f16x2 ex2; O += P@V (tensor);
            // l += sum(P) via fp32 ALU (HMMA is the binder, ALU has slack).
            float rs[2][2] = {{0.0f, 0.0f}, {0.0f, 0.0f}};
            #pragma unroll
            for (int g = 0; g < 4; g++) {
                unsigned ap[2][4];
                #pragma unroll
                for (int mi = 0; mi < 2; mi++) {
                    ap[mi][0] = hex2(pack_h2(s[mi][2*g][0]   - nm[mi][0],
                                             s[mi][2*g][1]   - nm[mi][0]));
                    ap[mi][1] = hex2(pack_h2(s[mi][2*g][2]   - nm[mi][1],
                                             s[mi][2*g][3]   - nm[mi][1]));
                    ap[mi][2] = hex2(pack_h2(s[mi][2*g+1][0] - nm[mi][0],
                                             s[mi][2*g+1][1] - nm[mi][0]));
                    ap[mi][3] = hex2(pack_h2(s[mi][2*g+1][2] - nm[mi][1],
                                             s[mi][2*g+1][3] - nm[mi][1]));

                    float2 p0 = __half22float2(*(__half2*)&ap[mi][0]);
                    float2 p1 = __half22float2(*(__half2*)&ap[mi][1]);
                    float2 p2 = __half22float2(*(__half2*)&ap[mi][2]);
                    float2 p3 = __half22float2(*(__half2*)&ap[mi][3]);
                    rs[mi][0] += (p0.x + p0.y) + (p2.x + p2.y);
                    rs[mi][1] += (p1.x + p1.y) + (p3.x + p3.y);
                }

                #pragma unroll
                for (int dg = 0; dg < 4; dg++) {
                    unsigned vf[4];
                    LDSM4T(vf, voff + g * 16 * RSTR + dg * 32);
                    unsigned b0[2] = { vf[0], vf[1] };
                    unsigned b1[2] = { vf[2], vf[3] };
                    mma16(o[0][2*dg],     ap[0], b0);
                    mma16(o[0][2*dg + 1], ap[0], b1);
                    mma16(o[1][2*dg],     ap[1], b0);
                    mma16(o[1][2*dg + 1], ap[1], b1);
                }
            }

            // Quad-reduce rs (lanes lm4=0..3 hold disjoint columns) and add
            #pragma unroll
            for (int mi = 0; mi < 2; mi++) {
                float r0 = rs[mi][0], r1 = rs[mi][1];
                #pragma unroll
                for (int off = 1; off < 4; off <<= 1) {
                    r0 += __shfl_xor_sync(0xffffffffu, r0, off);
                    r1 += __shfl_xor_sync(0xffffffffu, r1, off);
                }
                l[mi][0] += r0;
                l[mi][1] += r1;
            }
        }
    }

    // Epilogue
    #pragma unroll
    for (int mi = 0; mi < 2; mi++) {
        float i0 = 1.0f / l[mi][0];
        float i1 = 1.0f / l[mi][1];
        #pragma unroll
        for (int ni = 0; ni < 8; ni++) {
            int gr = b * SEQ + q0 + w32 + mi * 16 + l4;
            int gc = h * HDIM + ni * 8 + lm4 * 2;
            *(unsigned*)&O[(size_t)gr * EMBD + gc] =
                pack_h2(o[mi][ni][0] * i0, o[mi][ni][1] * i0);
            *(unsigned*)&O[(size_t)(gr + 8) * EMBD + gc] =
                pack_h2(o[mi][ni][2] * i1, o[mi][ni][3] * i1);
        }
    }
}

// ---------------------------------------------------------------------------
// Launch
// ---------------------------------------------------------------------------
extern "C" void kernel_launch(void* const* d_in, const int* in_sizes, int n_in,
                              void* d_out, int out_size)
{
    const float* x  = (const float*)d_in[0];
    const float* Wq = (const float*)d_in[1];
    const float* Wk = (const float*)d_in[2];
    const float* Wv = (const float*)d_in[3];
    const float* Wo = (const float*)d_in[4];
    float* out = (float*)d_out;

    __half *Qp, *Kp, *Vp, *Ap, *Xp, *Wp;
    cudaGetSymbolAddress((void**)&Qp, g_Q);
    cudaGetSymbolAddress((void**)&Kp, g_K);
    cudaGetSymbolAddress((void**)&Vp, g_V);
    cudaGetSymbolAddress((void**)&Ap, g_A);
    cudaGetSymbolAddress((void**)&Xp, g_X);
    cudaGetSymbolAddress((void**)&Wp, g_W);

    cudaFuncSetAttribute(gemm_qkv,   cudaFuncAttributeMaxDynamicSharedMemorySize, GSMEM);
    cudaFuncSetAttribute(gemm_out,   cudaFuncAttributeMaxDynamicSharedMemorySize, GSMEM);
    cudaFuncSetAttribute(attn_flash, cudaFuncAttributeMaxDynamicSharedMemorySize, ATTN_SMEM);

    prep<<<XBLKS4 + 4096, 256>>>((const float4*)x, (uint2*)Xp,
                                 Wq, Wk, Wv, Wo, Wp);

    dim3 gqkv((EMBD / 128) * 3, MROWS / 128);   // (24, 64), z fastest
    gemm_qkv<<<gqkv, 256, GSMEM>>>(Xp, Wp, Qp, Kp, Vp);

    dim3 ga(SEQ / 128, BATCH * NHEAD);          // (16, 64)
    attn_flash<<<ga, 128, ATTN_SMEM>>>(Qp, Kp, Vp, Ap);

    dim3 go(EMBD / 128, MROWS / 128);
    gemm_out<<<go, 256, GSMEM>>>(Ap, Wp + 3 * (size_t)EMBD * EMBD, out);
}

// round 16
// speedup vs baseline: 1.1132x; 1.1132x over previous
#include <cuda_runtime.h>
#include <cuda_fp16.h>
#include <math.h>
#include <stdint.h>

// ---------------------------------------------------------------------------
// MultiHeadAttention: x@Wq/Wk/Wv -> causal flash attention -> @Wo
// B=4, S=2048, E=1024, H=16, Hs=64. fp32 I/O, FP16 tensor-core math.
// R16: revert l to ones-MMA (R13). Weight transpose deleted: GEMM B operands
//      built via ldmatrix.trans from K-major [k][n] W (the proven V pattern),
//      prep is pure streaming elementwise (x + W converts, 4x ILP).
// ---------------------------------------------------------------------------

#define BATCH 4
#define SEQ   2048
#define EMBD  1024
#define NHEAD 16
#define HDIM  64
#define MROWS (BATCH*SEQ)   // 8192

#define QSCALE 0.18033688011112042f   // 0.125 * log2(e)

__device__ __align__(256) __half g_Q[MROWS * EMBD];
__device__ __align__(256) __half g_K[MROWS * EMBD];
__device__ __align__(256) __half g_V[MROWS * EMBD];
__device__ __align__(256) __half g_A[MROWS * EMBD];
__device__ __align__(256) __half g_X[MROWS * EMBD];
__device__ __align__(256) __half g_W[4 * EMBD * EMBD];   // fp16, [z][k][n] (NOT transposed)

__device__ __forceinline__ uint32_t s2u(const void* p) {
    return (uint32_t)__cvta_generic_to_shared(p);
}
#define CP16(dst, src) \
    asm volatile("cp.async.cg.shared.global [%0], [%1], 16;\n" :: "r"(dst), "l"(src))
#define CP_COMMIT()  asm volatile("cp.async.commit_group;\n" ::: "memory")
#define CP_WAIT(n)   asm volatile("cp.async.wait_group %0;\n" :: "n"(n) : "memory")

#define LDSM4(r, addr) \
    asm volatile("ldmatrix.sync.aligned.m8n8.x4.shared.b16 {%0,%1,%2,%3}, [%4];" \
        : "=r"((r)[0]), "=r"((r)[1]), "=r"((r)[2]), "=r"((r)[3]) : "r"(addr))
#define LDSM4T(r, addr) \
    asm volatile("ldmatrix.sync.aligned.m8n8.x4.trans.shared.b16 {%0,%1,%2,%3}, [%4];" \
        : "=r"((r)[0]), "=r"((r)[1]), "=r"((r)[2]), "=r"((r)[3]) : "r"(addr))

__device__ __forceinline__ void mma16(float* c, const unsigned* a, const unsigned* b) {
    asm volatile(
        "mma.sync.aligned.m16n8k16.row.col.f32.f16.f16.f32 "
        "{%0,%1,%2,%3}, {%4,%5,%6,%7}, {%8,%9}, {%0,%1,%2,%3};\n"
        : "+f"(c[0]), "+f"(c[1]), "+f"(c[2]), "+f"(c[3])
        : "r"(a[0]), "r"(a[1]), "r"(a[2]), "r"(a[3]),
          "r"(b[0]), "r"(b[1]));
}

__device__ __forceinline__ unsigned pack_h2(float lo, float hi) {
    __half2 h = __floats2half2_rn(lo, hi);
    return *(unsigned*)&h;
}

__device__ __forceinline__ float ex2f(float x) {
    float y;
    asm("ex2.approx.f32 %0, %1;" : "=f"(y) : "f"(x));
    return y;
}

__device__ __forceinline__ unsigned hex2(unsigned x) {
    unsigned y;
    asm("ex2.approx.f16x2 %0, %1;" : "=r"(y) : "r"(x));
    return y;
}

// ---------------------------------------------------------------------------
// Pure streaming pre-pass (no smem): blocks [0,2048) convert x (4x ILP);
// blocks [2048,3072) convert W matrices fp32->fp16 keeping [k][n] layout.
// ---------------------------------------------------------------------------
#define XBLKS4 2048   // (MROWS*EMBD/4) / 256 / 4
#define WBLKS4 1024   // (4*EMBD*EMBD/4) / 256 / 4 ; 256 blocks per matrix
__global__ __launch_bounds__(256) void prep(
    const float4* __restrict__ x, uint2* __restrict__ xout,
    const float* __restrict__ w0, const float* __restrict__ w1,
    const float* __restrict__ w2, const float* __restrict__ w3,
    uint2* __restrict__ wout)
{
    const int bid = blockIdx.x;
    if (bid < XBLKS4) {
        int i = bid * 1024 + threadIdx.x;
        float4 v0 = x[i];
        float4 v1 = x[i + 256];
        float4 v2 = x[i + 512];
        float4 v3 = x[i + 768];
        xout[i]       = make_uint2(pack_h2(v0.x, v0.y), pack_h2(v0.z, v0.w));
        xout[i + 256] = make_uint2(pack_h2(v1.x, v1.y), pack_h2(v1.z, v1.w));
        xout[i + 512] = make_uint2(pack_h2(v2.x, v2.y), pack_h2(v2.z, v2.w));
        xout[i + 768] = make_uint2(pack_h2(v3.x, v3.y), pack_h2(v3.z, v3.w));
    } else {
        const int wb = bid - XBLKS4;          // 0..1023
        const int z  = wb >> 8;               // 256 blocks per matrix
        const float4* in = (const float4*)((z == 0) ? w0 : (z == 1) ? w1
                                         : (z == 2) ? w2 : w3);
        const int li = (wb & 255) * 1024 + threadIdx.x;   // within matrix
        const int gi = wb * 1024 + threadIdx.x;           // within g_W
        float4 v0 = in[li];
        float4 v1 = in[li + 256];
        float4 v2 = in[li + 512];
        float4 v3 = in[li + 768];
        wout[gi]       = make_uint2(pack_h2(v0.x, v0.y), pack_h2(v0.z, v0.w));
        wout[gi + 256] = make_uint2(pack_h2(v1.x, v1.y), pack_h2(v1.z, v1.w));
        wout[gi + 512] = make_uint2(pack_h2(v2.x, v2.y), pack_h2(v2.z, v2.w));
        wout[gi + 768] = make_uint2(pack_h2(v3.x, v3.y), pack_h2(v3.z, v3.w));
    }
}

// ---------------------------------------------------------------------------
// FP16 GEMM body: C = A[m][k] @ W[k][n]. CTA 128x128, BK=64, 3-stage cp.async.
// A fragments via LDSM (K-major A tile); B fragments via LDSM.trans from the
// K-major [k][n] W tile (same pattern as the attention V operand).
// ---------------------------------------------------------------------------
#define ARSTR 144                      // A row: 64 k fp16 = 128B + 16 pad
#define BRSTR 272                      // B row: 128 n fp16 = 256B + 16 pad
#define A_TILE (128 * ARSTR)           // 18432
#define B_TILE (64 * BRSTR)            // 17408
#define STG_BYTES (A_TILE + B_TILE)    // 35840
#define GST 3
#define GSMEM (GST * STG_BYTES)        // 107520

template<bool HALF_OUT>
__device__ __forceinline__ void gemm_body(
    const __half* __restrict__ A, const __half* __restrict__ Wkn, void* __restrict__ Cv,
    float oscale, int m0, int n0)
{
    extern __shared__ __align__(1024) unsigned char sgm[];

    const int tid  = threadIdx.x;
    const int warp = tid >> 5;
    const int lane = tid & 31;
    const int l4   = lane >> 2;
    const int lm4  = lane & 3;
    const int wm0  = (warp >> 1) * 32;
    const int wn0  = (warp & 1) * 64;

    const int lrow = lane & 15;
    const int lcol = (lane >> 4) * 16;

    float acc[2][8][4];
    #pragma unroll
    for (int mi = 0; mi < 2; mi++)
        #pragma unroll
        for (int ni = 0; ni < 8; ni++)
            #pragma unroll
            for (int q = 0; q < 4; q++) acc[mi][ni][q] = 0.0f;

    const uint32_t sbase = s2u(sgm);

    auto load_stage = [&](int s, int k0) {
        uint32_t ab = sbase + s * STG_BYTES;
        uint32_t bb = ab + A_TILE;
        // A: 128 rows x 8 chunks of 16B
        #pragma unroll
        for (int t = 0; t < 4; t++) {
            int id = tid + t * 256;
            int r = id >> 3;
            int c = (id & 7) * 8;
            CP16(ab + r * ARSTR + c * 2, A + (size_t)(m0 + r) * EMBD + k0 + c);
        }
        // B: 64 k-rows x 16 chunks of 16B (128 n)
        #pragma unroll
        for (int t = 0; t < 4; t++) {
            int id = tid + t * 256;
            int r = id >> 4;
            int cb = (id & 15) * 16;
            CP16(bb + r * BRSTR + cb,
                 Wkn + (size_t)(k0 + r) * EMBD + n0 + (cb >> 1));
        }
        CP_COMMIT();
    };

    load_stage(0, 0);
    load_stage(1, 64);

    const int KT = EMBD / 64;  // 16
    for (int kt = 0; kt < KT; kt++) {
        const int s = kt % GST;
        if (kt < KT - 1) { CP_WAIT(1); } else { CP_WAIT(0); }
        __syncthreads();
        if (kt + 2 < KT) load_stage((kt + 2) % GST, (kt + 2) * 64);

        const uint32_t ab   = sbase + s * STG_BYTES;
        const uint32_t aoff = ab + (wm0 + lrow) * ARSTR + lcol;
        const uint32_t boff = ab + A_TILE + lrow * BRSTR + wn0 * 2 + lcol;

        #pragma unroll
        for (int kk = 0; kk < 4; kk++) {
            unsigned a0[4], a1[4];
            LDSM4(a0, aoff + kk * 32);
            LDSM4(a1, aoff + 16 * ARSTR + kk * 32);
            unsigned bf[4][4];
            #pragma unroll
            for (int ng = 0; ng < 4; ng++)
                LDSM4T(bf[ng], boff + kk * 16 * BRSTR + ng * 32);
            #pragma unroll
            for (int ni = 0; ni < 8; ni++) {
                unsigned b2[2] = { bf[ni >> 1][(ni & 1) * 2],
                                   bf[ni >> 1][(ni & 1) * 2 + 1] };
                mma16(acc[0][ni], a0, b2);
                mma16(acc[1][ni], a1, b2);
            }
        }
    }

    #pragma unroll
    for (int mi = 0; mi < 2; mi++) {
        #pragma unroll
        for (int ni = 0; ni < 8; ni++) {
            int row = m0 + wm0 + mi * 16 + l4;
            int col = n0 + wn0 + ni * 8 + lm4 * 2;
            if (HALF_OUT) {
                __half* C = (__half*)Cv;
                *(unsigned*)&C[(size_t)row * EMBD + col] =
                    pack_h2(acc[mi][ni][0] * oscale, acc[mi][ni][1] * oscale);
                *(unsigned*)&C[(size_t)(row + 8) * EMBD + col] =
                    pack_h2(acc[mi][ni][2] * oscale, acc[mi][ni][3] * oscale);
            } else {
                float* C = (float*)Cv;
                *(float2*)&C[(size_t)row * EMBD + col] =
                    make_float2(acc[mi][ni][0], acc[mi][ni][1]);
                *(float2*)&C[(size_t)(row + 8) * EMBD + col] =
                    make_float2(acc[mi][ni][2], acc[mi][ni][3]);
            }
        }
    }
}

__global__ __launch_bounds__(256, 2) void gemm_qkv(
    const __half* __restrict__ X, const __half* __restrict__ W,
    __half* __restrict__ C0, __half* __restrict__ C1, __half* __restrict__ C2)
{
    const int z  = blockIdx.x % 3;
    const int n0 = (blockIdx.x / 3) * 128;
    const int m0 = blockIdx.y * 128;
    const __half* Wz = W + (size_t)z * EMBD * EMBD;
    __half* C = (z == 0) ? C0 : (z == 1) ? C1 : C2;
    float sc = (z == 0) ? QSCALE : 1.0f;
    gemm_body<true>(X, Wz, C, sc, m0, n0);
}

__global__ __launch_bounds__(256, 2) void gemm_out(
    const __half* __restrict__ A, const __half* __restrict__ W, float* __restrict__ C)
{
    gemm_body<false>(A, W, C, 1.0f, blockIdx.y * 128, blockIdx.x * 128);
}

// ---------------------------------------------------------------------------
// Causal flash attention (R13 form: ones-MMA l, Q fragments hoisted).
// One CTA = 128 q-rows, 128 threads = 4 warps x 32 q-rows, 128-key blocks.
// ---------------------------------------------------------------------------
#define RSTR 144
#define QTB (128 * RSTR)               // 18432
#define KTB (64 * RSTR)                // 9216 per 64-key subtile
#define KVBLK (2 * KTB)                // 128-key block
#define ATTN_SMEM (QTB + 4 * KVBLK)    // 92160 bytes

__global__ __launch_bounds__(128, 2) void attn_flash(
    const __half* __restrict__ Q, const __half* __restrict__ K,
    const __half* __restrict__ V, __half* __restrict__ O)
{
    extern __shared__ __align__(1024) unsigned char sgm[];
    const uint32_t qbase = s2u(sgm);
    const uint32_t kbase = qbase + QTB;
    const uint32_t vbase = kbase + 2 * KVBLK;

    const int tid  = threadIdx.x;
    const int warp = tid >> 5;
    const int lane = tid & 31;
    const int l4   = lane >> 2;
    const int lm4  = lane & 3;
    const int w32  = warp * 32;

    const int lrow = lane & 15;
    const int lcol = (lane >> 4) * 16;

    const int qb = (gridDim.x - 1) - blockIdx.x;   // longest blocks first
    const int q0 = qb * 128;
    const int bh = blockIdx.y;
    const int b  = bh >> 4;
    const int h  = bh & 15;
    const size_t headoff = (size_t)b * SEQ * EMBD + (size_t)h * HDIM;

    const unsigned ONESH2 = 0x3C003C00u;

    #pragma unroll
    for (int t = 0; t < 8; t++) {
        int idx = tid + t * 128;
        int r = idx >> 3;
        int c = (idx & 7) * 8;
        *(uint4*)(sgm + r * RSTR + c * 2) =
            *(const uint4*)(Q + headoff + (size_t)(q0 + r) * EMBD + c);
    }

    auto load_kv2 = [&](int jj, int s) {
        #pragma unroll
        for (int t = 0; t < 8; t++) {
            int id = tid + t * 128;
            int r = id >> 3;
            int c = (id & 7) * 8;
            CP16(kbase + s * KVBLK + r * RSTR + c * 2,
                 K + headoff + (size_t)(jj * 128 + r) * EMBD + c);
        }
        #pragma unroll
        for (int t = 0; t < 8; t++) {
            int id = tid + t * 128;
            int r = id >> 3;
            int c = (id & 7) * 8;
            CP16(vbase + s * KVBLK + r * RSTR + c * 2,
                 V + headoff + (size_t)(jj * 128 + r) * EMBD + c);
        }
        CP_COMMIT();
    };

    float m[2][2] = {{-INFINITY, -INFINITY}, {-INFINITY, -INFINITY}};
    float o[2][8][4];
    float lacc[2][4];
    #pragma unroll
    for (int mi = 0; mi < 2; mi++) {
        #pragma unroll
        for (int ni = 0; ni < 8; ni++)
            #pragma unroll
            for (int q = 0; q < 4; q++) o[mi][ni][q] = 0.0f;
        #pragma unroll
        for (int q = 0; q < 4; q++) lacc[mi][q] = 0.0f;
    }

    const int njj = qb + 1;
    load_kv2(0, 0);

    // Hoist Q fragments (loop-invariant)
    __syncthreads();
    unsigned qf[2][4][4];
    {
        const uint32_t qoff0 = qbase + (w32 + lrow) * RSTR + lcol;
        const uint32_t qoff1 = qoff0 + 16 * RSTR;
        #pragma unroll
        for (int kk = 0; kk < 4; kk++) {
            LDSM4(qf[0][kk], qoff0 + kk * 32);
            LDSM4(qf[1][kk], qoff1 + kk * 32);
        }
    }

    for (int jj = 0; jj < njj; jj++) {
        CP_WAIT(0);
        __syncthreads();
        if (jj + 1 < njj) load_kv2(jj + 1, (jj + 1) & 1);

        #pragma unroll
        for (int hs = 0; hs < 2; hs++) {
            const int j = 2 * jj + hs;

            if (j * 64 > q0 + w32 + 31) continue;

            const uint32_t koff = kbase + (jj & 1) * KVBLK + hs * KTB
                                + lrow * RSTR + lcol;
            const uint32_t voff = vbase + (jj & 1) * KVBLK + hs * KTB
                                + lrow * RSTR + lcol;

            float s[2][8][4];
            #pragma unroll
            for (int mi = 0; mi < 2; mi++)
                #pragma unroll
                for (int ni = 0; ni < 8; ni++)
                    #pragma unroll
                    for (int q = 0; q < 4; q++) s[mi][ni][q] = 0.0f;

            #pragma unroll
            for (int kk = 0; kk < 4; kk++) {
                unsigned bf[4][4];
                #pragma unroll
                for (int ng = 0; ng < 4; ng++)
                    LDSM4(bf[ng], koff + ng * 16 * RSTR + kk * 32);
                #pragma unroll
                for (int ni = 0; ni < 8; ni++) {
                    unsigned b2[2] = { bf[ni >> 1][ni & 1], bf[ni >> 1][(ni & 1) + 2] };
                    mma16(s[0][ni], qf[0][kk], b2);
                    mma16(s[1][ni], qf[1][kk], b2);
                }
            }

            if (j * 64 + 63 > q0 + w32) {
                #pragma unroll
                for (int mi = 0; mi < 2; mi++) {
                    const int g0 = q0 + w32 + mi * 16 + l4;
                    const int g1 = g0 + 8;
                    #pragma unroll
                    for (int ni = 0; ni < 8; ni++) {
                        int gc = j * 64 + ni * 8 + lm4 * 2;
                        if (gc     > g0) s[mi][ni][0] = -INFINITY;
                        if (gc + 1 > g0) s[mi][ni][1] = -INFINITY;
                        if (gc     > g1) s[mi][ni][2] = -INFINITY;
                        if (gc + 1 > g1) s[mi][ni][3] = -INFINITY;
                    }
                }
            }

            float a[2][2], nm[2][2];
            #pragma unroll
            for (int mi = 0; mi < 2; mi++) {
                float rm0 = -INFINITY, rm1 = -INFINITY;
                #pragma unroll
                for (int ni = 0; ni < 8; ni++) {
                    rm0 = fmaxf(rm0, fmaxf(s[mi][ni][0], s[mi][ni][1]));
                    rm1 = fmaxf(rm1, fmaxf(s[mi][ni][2], s[mi][ni][3]));
                }
                #pragma unroll
                for (int off = 1; off < 4; off <<= 1) {
                    rm0 = fmaxf(rm0, __shfl_xor_sync(0xffffffffu, rm0, off));
                    rm1 = fmaxf(rm1, __shfl_xor_sync(0xffffffffu, rm1, off));
                }
                nm[mi][0] = fmaxf(m[mi][0], rm0);
                nm[mi][1] = fmaxf(m[mi][1], rm1);
                a[mi][0] = ex2f(m[mi][0] - nm[mi][0]);
                a[mi][1] = ex2f(m[mi][1] - nm[mi][1]);
                m[mi][0] = nm[mi][0];
                m[mi][1] = nm[mi][1];
            }

            bool noresc = (a[0][0] == 1.0f) && (a[0][1] == 1.0f)
                       && (a[1][0] == 1.0f) && (a[1][1] == 1.0f);
            if (!__all_sync(0xffffffffu, noresc)) {
                #pragma unroll
                for (int mi = 0; mi < 2; mi++) {
                    #pragma unroll
                    for (int ni = 0; ni < 8; ni++) {
                        o[mi][ni][0] *= a[mi][0]; o[mi][ni][1] *= a[mi][0];
                        o[mi][ni][2] *= a[mi][1]; o[mi][ni][3] *= a[mi][1];
                    }
                    lacc[mi][0] *= a[mi][0]; lacc[mi][1] *= a[mi][0];
                    lacc[mi][2] *= a[mi][1]; lacc[mi][3] *= a[mi][1];
                }
            }

            #pragma unroll
            for (int g = 0; g < 4; g++) {
                unsigned ap[2][4];
                #pragma unroll
                for (int mi = 0; mi < 2; mi++) {
                    ap[mi][0] = hex2(pack_h2(s[mi][2*g][0]   - nm[mi][0],
                                             s[mi][2*g][1]   - nm[mi][0]));
                    ap[mi][1] = hex2(pack_h2(s[mi][2*g][2]   - nm[mi][1],
                                             s[mi][2*g][3]   - nm[mi][1]));
                    ap[mi][2] = hex2(pack_h2(s[mi][2*g+1][0] - nm[mi][0],
                                             s[mi][2*g+1][1] - nm[mi][0]));
                    ap[mi][3] = hex2(pack_h2(s[mi][2*g+1][2] - nm[mi][1],
                                             s[mi][2*g+1][3] - nm[mi][1]));
                }

                unsigned ones2[2] = { ONESH2, ONESH2 };
                mma16(lacc[0], ap[0], ones2);
                mma16(lacc[1], ap[1], ones2);

                #pragma unroll
                for (int dg = 0; dg < 4; dg++) {
                    unsigned vf[4];
                    LDSM4T(vf, voff + g * 16 * RSTR + dg * 32);
                    unsigned b0[2] = { vf[0], vf[1] };
                    unsigned b1[2] = { vf[2], vf[3] };
                    mma16(o[0][2*dg],     ap[0], b0);
                    mma16(o[0][2*dg + 1], ap[0], b1);
                    mma16(o[1][2*dg],     ap[1], b0);
                    mma16(o[1][2*dg + 1], ap[1], b1);
                }
            }
        }
    }

    #pragma unroll
    for (int mi = 0; mi < 2; mi++) {
        float i0 = 1.0f / lacc[mi][0];
        float i1 = 1.0f / lacc[mi][2];
        #pragma unroll
        for (int ni = 0; ni < 8; ni++) {
            int gr = b * SEQ + q0 + w32 + mi * 16 + l4;
            int gc = h * HDIM + ni * 8 + lm4 * 2;
            *(unsigned*)&O[(size_t)gr * EMBD + gc] =
                pack_h2(o[mi][ni][0] * i0, o[mi][ni][1] * i0);
            *(unsigned*)&O[(size_t)(gr + 8) * EMBD + gc] =
                pack_h2(o[mi][ni][2] * i1, o[mi][ni][3] * i1);
        }
    }
}

// ---------------------------------------------------------------------------
// Launch
// ---------------------------------------------------------------------------
extern "C" void kernel_launch(void* const* d_in, const int* in_sizes, int n_in,
                              void* d_out, int out_size)
{
    const float* x  = (const float*)d_in[0];
    const float* Wq = (const float*)d_in[1];
    const float* Wk = (const float*)d_in[2];
    const float* Wv = (const float*)d_in[3];
    const float* Wo = (const float*)d_in[4];
    float* out = (float*)d_out;

    __half *Qp, *Kp, *Vp, *Ap, *Xp, *Wp;
    cudaGetSymbolAddress((void**)&Qp, g_Q);
    cudaGetSymbolAddress((void**)&Kp, g_K);
    cudaGetSymbolAddress((void**)&Vp, g_V);
    cudaGetSymbolAddress((void**)&Ap, g_A);
    cudaGetSymbolAddress((void**)&Xp, g_X);
    cudaGetSymbolAddress((void**)&Wp, g_W);

    cudaFuncSetAttribute(gemm_qkv,   cudaFuncAttributeMaxDynamicSharedMemorySize, GSMEM);
    cudaFuncSetAttribute(gemm_out,   cudaFuncAttributeMaxDynamicSharedMemorySize, GSMEM);
    cudaFuncSetAttribute(attn_flash, cudaFuncAttributeMaxDynamicSharedMemorySize, ATTN_SMEM);

    prep<<<XBLKS4 + WBLKS4, 256>>>((const float4*)x, (uint2*)Xp,
                                   Wq, Wk, Wv, Wo, (uint2*)Wp);

    dim3 gqkv((EMBD / 128) * 3, MROWS / 128);   // (24, 64), z fastest
    gemm_qkv<<<gqkv, 256, GSMEM>>>(Xp, Wp, Qp, Kp, Vp);

    dim3 ga(SEQ / 128, BATCH * NHEAD);          // (16, 64)
    attn_flash<<<ga, 128, ATTN_SMEM>>>(Qp, Kp, Vp, Ap);

    dim3 go(EMBD / 128, MROWS / 128);
    gemm_out<<<go, 256, GSMEM>>>(Ap, Wp + 3 * (size_t)EMBD * EMBD, out);
}